// round 7
// baseline (speedup 1.0000x reference)
#include <cuda_runtime.h>
#include <cstdint>

// x: (B=8, H=256, W=256, C=64) fp32, WIN=16, half=8
// out: (B, 961, 16*16*64) fp32, partition order (0,0),(0,8),(8,0),(8,8)
// windows per partition: 256, 240, 240, 225 -> 961 per batch (7688 total)
//
// Persistent TMA pipeline: 444 CTAs (3/SM, 64KB smem each). Per window:
// 16x cp.async.bulk g->s (4KB rows, mbarrier-counted) then one 64KB
// cp.async.bulk s->g. Key overlap: wait_group.read only waits for TMA to
// finish READING smem, so window k's DRAM write drains while window k+1's
// reads are in flight. Grid-stride of 444 keeps the concurrent write span
// contiguous (~29MB) and preserves L2 reuse of the input slice.

#define NPB 961
#define NWIN (8 * NPB)               // 7688
#define NBLK 444                     // 148 SMs * 3 CTAs
#define IMG_ROW_BYTES (256 * 64 * 4) // 65536 B per input image row
#define WROW_BYTES    (16 * 64 * 4)  // 4096 B per window row
#define WIN_BYTES     (16 * WROW_BYTES)
#define SMEM_BUF_OFF  128
#define SMEM_TOTAL    (SMEM_BUF_OFF + WIN_BYTES)

__global__ void __launch_bounds__(32)
partition_tma_kernel(const char* __restrict__ x, char* __restrict__ out)
{
    extern __shared__ char smem[];
    const uint32_t smem_base = (uint32_t)__cvta_generic_to_shared(smem);
    const uint32_t mbar = smem_base;                 // 8B mbarrier
    const uint32_t buf  = smem_base + SMEM_BUF_OFF;  // 64KB window buffer

    if (threadIdx.x != 0) return;   // single orchestration thread per CTA

    asm volatile("mbarrier.init.shared.b64 [%0], 1;" :: "r"(mbar) : "memory");
    asm volatile("fence.proxy.async.shared::cta;" ::: "memory");

    uint32_t parity = 0;

    for (int blk = blockIdx.x; blk < NWIN; blk += NBLK) {
        const int b = blk / NPB;
        const int p = blk - b * NPB;

        int r0, c0, nc, base;
        if (p < 256)      { r0 = 0; c0 = 0; nc = 16; base = 0;   }
        else if (p < 496) { r0 = 0; c0 = 8; nc = 15; base = 256; }
        else if (p < 736) { r0 = 8; c0 = 0; nc = 16; base = 496; }
        else              { r0 = 8; c0 = 8; nc = 15; base = 736; }

        const int q  = p - base;
        const int wr = q / nc;
        const int wc = q - wr * nc;
        const int row0 = r0 + wr * 16;
        const int col0 = c0 + wc * 16;

        const char* src = x
            + (size_t)(b * 256 + row0) * IMG_ROW_BYTES
            + (size_t)col0 * (64 * 4);
        char* dst = out + (size_t)blk * WIN_BYTES;

        // Buffer reuse gate: previous store must have finished READING smem
        // (its DRAM write keeps draining in the background).
        asm volatile("cp.async.bulk.wait_group.read 0;" ::: "memory");

        asm volatile("mbarrier.arrive.expect_tx.shared.b64 _, [%0], %1;"
                     :: "r"(mbar), "r"((uint32_t)WIN_BYTES) : "memory");
#pragma unroll
        for (int i = 0; i < 16; ++i) {
            asm volatile(
                "cp.async.bulk.shared::cta.global.mbarrier::complete_tx::bytes "
                "[%0], [%1], %2, [%3];"
                :: "r"(buf + i * WROW_BYTES),
                   "l"(src + (size_t)i * IMG_ROW_BYTES),
                   "r"((uint32_t)WROW_BYTES),
                   "r"(mbar)
                : "memory");
        }

        // Wait for all 16 rows (alternating parity per iteration).
        asm volatile(
            "{\n\t.reg .pred P;\n\t"
            "WAITLOOP%=:\n\t"
            "mbarrier.try_wait.parity.shared.b64 P, [%0], %1, 0x989680;\n\t"
            "@!P bra WAITLOOP%=;\n\t}"
            :: "r"(mbar), "r"(parity) : "memory");
        parity ^= 1;

        // 64KB sequential bulk store; do NOT wait for its completion here.
        asm volatile(
            "cp.async.bulk.global.shared::cta.bulk_group [%0], [%1], %2;"
            :: "l"(dst), "r"(buf), "r"((uint32_t)WIN_BYTES) : "memory");
        asm volatile("cp.async.bulk.commit_group;" ::: "memory");
    }

    // Drain: ensure final store has read smem before CTA teardown.
    asm volatile("cp.async.bulk.wait_group.read 0;" ::: "memory");
}

extern "C" void kernel_launch(void* const* d_in, const int* in_sizes, int n_in,
                              void* d_out, int out_size)
{
    const char* x = (const char*)d_in[0];
    char* out = (char*)d_out;
    cudaFuncSetAttribute(partition_tma_kernel,
                         cudaFuncAttributeMaxDynamicSharedMemorySize, SMEM_TOTAL);
    partition_tma_kernel<<<NBLK, 32, SMEM_TOTAL>>>(x, out);
}

// round 8
// speedup vs baseline: 1.3520x; 1.3520x over previous
#include <cuda_runtime.h>
#include <cstdint>

// x: (B=8, H=256, W=256, C=64) fp32, WIN=16, half=8
// out: (B, 961, 16*16*64) fp32, partition order (0,0),(0,8),(8,0),(8,8)
// windows per partition: 256, 240, 240, 225 -> 961 per batch
//
// R2 skeleton (best: 94.9us, DRAM 80.4%): one-shot block per window,
// 16 front-batched LDG.128 + 16 streaming STG.128. R2 compiled to 72 regs,
// which already fits 3 CTAs/SM -- only the (256,2) hint capped residency.
// This round: __launch_bounds__(256,3) -> 3 CTAs/SM at (expected) identical
// SASS, raising concurrent request streams 50% at constant per-warp MLP.

#define Hh 256
#define Ww 256
#define Cc 64
#define NPB 961                // windows per batch
#define ROW_F4 (Ww * Cc / 4)   // float4 per input image row = 4096

__global__ void __launch_bounds__(256, 3)
partition_kernel(const float* __restrict__ x, float* __restrict__ out)
{
    const int blk = blockIdx.x;            // b * 961 + p
    const int b   = blk / NPB;
    const int p   = blk - b * NPB;

    int r0, c0, nc, base;
    if (p < 256)      { r0 = 0; c0 = 0; nc = 16; base = 0;   }
    else if (p < 496) { r0 = 0; c0 = 8; nc = 15; base = 256; }
    else if (p < 736) { r0 = 8; c0 = 0; nc = 16; base = 496; }
    else              { r0 = 8; c0 = 8; nc = 15; base = 736; }

    const int q  = p - base;
    const int wr = q / nc;
    const int wc = q - wr * nc;
    const int row0 = r0 + wr * 16;
    const int col0 = c0 + wc * 16;

    const float4* __restrict__ src =
        reinterpret_cast<const float4*>(x) +
        (size_t)(b * Hh + row0) * ROW_F4 + (size_t)col0 * (Cc / 4);
    float4* __restrict__ dst =
        reinterpret_cast<float4*>(out) + (size_t)blk * (16 * 16 * Cc / 4);

    const int t = threadIdx.x;             // 0..255: one float4 of the 4KB row

    // Front-batch ALL 16 independent LDG.128s, then drain with 16
    // streaming STG.128s (evict-first: keeps reused input slice in L2).
    float4 v[16];
#pragma unroll
    for (int i = 0; i < 16; ++i)
        v[i] = __ldg(&src[(size_t)i * ROW_F4 + t]);
#pragma unroll
    for (int i = 0; i < 16; ++i)
        __stcs(&dst[i * 256 + t], v[i]);
}

extern "C" void kernel_launch(void* const* d_in, const int* in_sizes, int n_in,
                              void* d_out, int out_size)
{
    const float* x = (const float*)d_in[0];
    float* out = (float*)d_out;
    const int nblocks = 8 * NPB;           // 7688
    partition_kernel<<<nblocks, 256>>>(x, out);
}